// round 2
// baseline (speedup 1.0000x reference)
#include <cuda_runtime.h>

#define BB 512
#define NN 90
#define DD 1024
#define KK 45
#define THREADS 512
#define WARPS 16

// Dummy dynamic smem request to force 1 CTA/SM: 2 CTAs would need ~250KB > 228KB.
#define SMEM_PAD (125 * 1024)

__global__ __launch_bounds__(THREADS, 1)
void multig_pool_kernel(const float* __restrict__ x_sc,
                        const float* __restrict__ x_fc,
                        const float* __restrict__ pool_w,
                        const float* __restrict__ multi_w,
                        const float* __restrict__ multi_b,
                        float* __restrict__ out)
{
    extern __shared__ float dyn_pad[];        // occupancy limiter (unused)
    __shared__ __align__(16) float spw[DD];   // pool_w staged in smem
    __shared__ float scores[NN];
    __shared__ int   sel_idx[KK];
    __shared__ float sel_w[KK];
    __shared__ float red[WARPS];
    __shared__ float s_invnorm;

    const int b    = blockIdx.x;
    const int tid  = threadIdx.x;
    const int wid  = tid >> 5;
    const int lane = tid & 31;

    // ---- Phase 0: stage pool_w, compute 1/||pool_w|| ----
    float pw2 = 0.f;
    {
        float v0 = pool_w[tid];
        float v1 = pool_w[tid + THREADS];
        spw[tid]           = v0;
        spw[tid + THREADS] = v1;
        pw2 = v0 * v0 + v1 * v1;
    }
    #pragma unroll
    for (int off = 16; off; off >>= 1) pw2 += __shfl_xor_sync(0xffffffffu, pw2, off);
    if (lane == 0) red[wid] = pw2;
    __syncthreads();
    if (tid == 0) {
        float s = 0.f;
        #pragma unroll
        for (int i = 0; i < WARPS; i++) s += red[i];
        s_invnorm = rsqrtf(s);
    }
    __syncthreads();

    const float inv_norm = s_invnorm;
    const float mw0 = multi_w[0];
    const float mw1 = multi_w[1];

    const float* __restrict__ xb_sc = x_sc + (size_t)b * NN * DD;
    const float* __restrict__ xb_fc = x_fc + (size_t)b * NN * DD;

    // ---- Phase 1: per-node dual dot-products (warp per node, strided) ----
    const float4* __restrict__ pw4 = (const float4*)spw;
    for (int n = wid; n < NN; n += WARPS) {
        const float4* rs = (const float4*)(xb_sc + (size_t)n * DD);
        const float4* rf = (const float4*)(xb_fc + (size_t)n * DD);
        float dsc = 0.f, dfc = 0.f;
        #pragma unroll
        for (int i = 0; i < 8; i++) {
            int j = lane + i * 32;
            float4 a = rs[j];
            float4 c = rf[j];
            float4 p = pw4[j];
            dsc += a.x * p.x + a.y * p.y + a.z * p.z + a.w * p.w;
            dfc += c.x * p.x + c.y * p.y + c.z * p.z + c.w * p.w;
        }
        #pragma unroll
        for (int off = 16; off; off >>= 1) {
            dsc += __shfl_xor_sync(0xffffffffu, dsc, off);
            dfc += __shfl_xor_sync(0xffffffffu, dfc, off);
        }
        if (lane == 0) {
            float t0 = tanhf(dsc * inv_norm);
            float t1 = tanhf(dfc * inv_norm);
            float z  = t0 * mw0 + t1 * mw1 + multi_b[n];
            scores[n] = 1.f / (1.f + expf(-z));
        }
    }
    __syncthreads();

    // ---- Phase 2: rank-count selection (stable descending argsort match) ----
    if (tid < NN) {
        float my = scores[tid];
        int rank = 0;
        #pragma unroll 10
        for (int j = 0; j < NN; j++) {
            float sj = scores[j];
            rank += (sj > my) || (sj == my && j < tid);
        }
        if (rank < KK) { sel_idx[rank] = tid; sel_w[rank] = my; }
    }
    __syncthreads();

    // ---- Phase 3: gather+scale selected rows (warp per output row) ----
    // Reads should hit L2 (rows scored by this CTA are still resident at
    // 1 CTA/SM: 148 x 737KB = 109MB < 126MB L2). Stores use .cs streaming
    // policy so the 189MB of output doesn't evict the resident inputs.
    float* __restrict__ out_sc = out + (size_t)b * KK * DD;
    float* __restrict__ out_fc = out + (size_t)BB * KK * DD + (size_t)b * KK * DD;

    for (int r = wid; r < 2 * KK; r += WARPS) {
        const bool is_sc = (r < KK);
        const int  k = is_sc ? r : r - KK;
        const int  n = sel_idx[k];
        const float w = sel_w[k];
        const float4* src = (const float4*)((is_sc ? xb_sc : xb_fc) + (size_t)n * DD);
        float4* dst = (float4*)((is_sc ? out_sc : out_fc) + (size_t)k * DD);
        #pragma unroll
        for (int i = 0; i < 8; i++) {
            int j = lane + i * 32;
            float4 v = __ldcg(src + j);
            v.x *= w; v.y *= w; v.z *= w; v.w *= w;
            __stcs(dst + j, v);
        }
    }
    (void)dyn_pad;
}

extern "C" void kernel_launch(void* const* d_in, const int* in_sizes, int n_in,
                              void* d_out, int out_size)
{
    const float* x_sc    = (const float*)d_in[0];
    const float* x_fc    = (const float*)d_in[1];
    const float* pool_w  = (const float*)d_in[2];
    const float* multi_w = (const float*)d_in[3];
    const float* multi_b = (const float*)d_in[4];
    float* out = (float*)d_out;

    static int smem_set = 0;
    if (!smem_set) {
        cudaFuncSetAttribute(multig_pool_kernel,
                             cudaFuncAttributeMaxDynamicSharedMemorySize, SMEM_PAD);
        smem_set = 1;
    }

    multig_pool_kernel<<<BB, THREADS, SMEM_PAD>>>(x_sc, x_fc, pool_w, multi_w, multi_b, out);
}

// round 3
// speedup vs baseline: 1.0159x; 1.0159x over previous
#include <cuda_runtime.h>

#define BB 512
#define NN 90
#define DD 1024
#define KK 45
#define THREADS 512
#define WARPS 16

__global__ __launch_bounds__(THREADS, 2)
void multig_pool_kernel(const float* __restrict__ x_sc,
                        const float* __restrict__ x_fc,
                        const float* __restrict__ pool_w,
                        const float* __restrict__ multi_w,
                        const float* __restrict__ multi_b,
                        float* __restrict__ out)
{
    __shared__ __align__(16) float spw[DD];   // pool_w staged in smem
    __shared__ float scores[NN];
    __shared__ int   sel_idx[KK];
    __shared__ float sel_w[KK];
    __shared__ float red[WARPS];
    __shared__ float s_invnorm;

    const int b    = blockIdx.x;
    const int tid  = threadIdx.x;
    const int wid  = tid >> 5;
    const int lane = tid & 31;

    // ---- Phase 0: stage pool_w, compute 1/||pool_w|| ----
    float pw2 = 0.f;
    {
        float v0 = pool_w[tid];
        float v1 = pool_w[tid + THREADS];
        spw[tid]           = v0;
        spw[tid + THREADS] = v1;
        pw2 = v0 * v0 + v1 * v1;
    }
    #pragma unroll
    for (int off = 16; off; off >>= 1) pw2 += __shfl_xor_sync(0xffffffffu, pw2, off);
    if (lane == 0) red[wid] = pw2;
    __syncthreads();
    if (tid == 0) {
        float s = 0.f;
        #pragma unroll
        for (int i = 0; i < WARPS; i++) s += red[i];
        s_invnorm = rsqrtf(s);
    }
    __syncthreads();

    const float inv_norm = s_invnorm;
    const float mw0 = multi_w[0];
    const float mw1 = multi_w[1];

    const float* __restrict__ xb_sc = x_sc + (size_t)b * NN * DD;
    const float* __restrict__ xb_fc = x_fc + (size_t)b * NN * DD;

    // ---- Phase 1: per-node dual dot-products (warp per node, strided).
    // Default loads: populate L2 so the gather below can hit. ----
    const float4* __restrict__ pw4 = (const float4*)spw;
    for (int n = wid; n < NN; n += WARPS) {
        const float4* rs = (const float4*)(xb_sc + (size_t)n * DD);
        const float4* rf = (const float4*)(xb_fc + (size_t)n * DD);
        float dsc = 0.f, dfc = 0.f;
        #pragma unroll
        for (int i = 0; i < 8; i++) {
            int j = lane + i * 32;
            float4 a = rs[j];
            float4 c = rf[j];
            float4 p = pw4[j];
            dsc += a.x * p.x + a.y * p.y + a.z * p.z + a.w * p.w;
            dfc += c.x * p.x + c.y * p.y + c.z * p.z + c.w * p.w;
        }
        #pragma unroll
        for (int off = 16; off; off >>= 1) {
            dsc += __shfl_xor_sync(0xffffffffu, dsc, off);
            dfc += __shfl_xor_sync(0xffffffffu, dfc, off);
        }
        if (lane == 0) {
            float t0 = tanhf(dsc * inv_norm);
            float t1 = tanhf(dfc * inv_norm);
            float z  = t0 * mw0 + t1 * mw1 + multi_b[n];
            scores[n] = 1.f / (1.f + expf(-z));
        }
    }
    __syncthreads();

    // ---- Phase 2: rank-count selection (stable descending argsort match) ----
    if (tid < NN) {
        float my = scores[tid];
        int rank = 0;
        #pragma unroll 10
        for (int j = 0; j < NN; j++) {
            float sj = scores[j];
            rank += (sj > my) || (sj == my && j < tid);
        }
        if (rank < KK) { sel_idx[rank] = tid; sel_w[rank] = my; }
    }
    __syncthreads();

    // ---- Phase 3: gather+scale selected rows (warp per output row).
    // __ldlu: last-use read, release L2 line after this read.
    // __stcs: streaming store, don't let the 189MB output evict inputs. ----
    float* __restrict__ out_sc = out + (size_t)b * KK * DD;
    float* __restrict__ out_fc = out + (size_t)BB * KK * DD + (size_t)b * KK * DD;

    for (int r = wid; r < 2 * KK; r += WARPS) {
        const bool is_sc = (r < KK);
        const int  k = is_sc ? r : r - KK;
        const int  n = sel_idx[k];
        const float w = sel_w[k];
        const float4* src = (const float4*)((is_sc ? xb_sc : xb_fc) + (size_t)n * DD);
        float4* dst = (float4*)((is_sc ? out_sc : out_fc) + (size_t)k * DD);
        #pragma unroll
        for (int i = 0; i < 8; i++) {
            int j = lane + i * 32;
            float4 v = __ldlu(src + j);
            v.x *= w; v.y *= w; v.z *= w; v.w *= w;
            __stcs(dst + j, v);
        }
    }
}

extern "C" void kernel_launch(void* const* d_in, const int* in_sizes, int n_in,
                              void* d_out, int out_size)
{
    const float* x_sc    = (const float*)d_in[0];
    const float* x_fc    = (const float*)d_in[1];
    const float* pool_w  = (const float*)d_in[2];
    const float* multi_w = (const float*)d_in[3];
    const float* multi_b = (const float*)d_in[4];
    float* out = (float*)d_out;

    multig_pool_kernel<<<BB, THREADS>>>(x_sc, x_fc, pool_w, multi_w, multi_b, out);
}

// round 4
// speedup vs baseline: 1.2249x; 1.2058x over previous
#include <cuda_runtime.h>

#define BB 512
#define NN 90
#define DD 1024
#define KK 45
#define THREADS 512
#define WARPS 16
#define N_SCORE_TASKS  BB
#define N_GATHER_TASKS (BB * 2)
#define TOTAL_TASKS    (N_SCORE_TASKS + N_GATHER_TASKS)

// Scratch (device globals — no allocation allowed)
__device__ unsigned g_task_counter;
__device__ unsigned g_flags[BB];
__device__ int      g_sel_idx[BB][KK];
__device__ float    g_sel_w[BB][KK];

__global__ void init_kernel()
{
    int t = blockIdx.x * blockDim.x + threadIdx.x;
    if (t == 0) g_task_counter = 0;
    if (t < BB) g_flags[t] = 0;
}

__global__ __launch_bounds__(THREADS, 2)
void multig_pool_kernel(const float* __restrict__ x_sc,
                        const float* __restrict__ x_fc,
                        const float* __restrict__ pool_w,
                        const float* __restrict__ multi_w,
                        const float* __restrict__ multi_b,
                        float* __restrict__ out)
{
    __shared__ __align__(16) float spw[DD];
    __shared__ float scores[NN];
    __shared__ float red[WARPS];
    __shared__ float s_invnorm;
    __shared__ unsigned s_task;

    const int tid  = threadIdx.x;
    const int wid  = tid >> 5;
    const int lane = tid & 31;

    // ---- Once per CTA: stage pool_w, compute 1/||pool_w|| ----
    float pw2 = 0.f;
    {
        float v0 = pool_w[tid];
        float v1 = pool_w[tid + THREADS];
        spw[tid]           = v0;
        spw[tid + THREADS] = v1;
        pw2 = v0 * v0 + v1 * v1;
    }
    #pragma unroll
    for (int off = 16; off; off >>= 1) pw2 += __shfl_xor_sync(0xffffffffu, pw2, off);
    if (lane == 0) red[wid] = pw2;
    __syncthreads();
    if (tid == 0) {
        float s = 0.f;
        #pragma unroll
        for (int i = 0; i < WARPS; i++) s += red[i];
        s_invnorm = rsqrtf(s);
    }
    __syncthreads();

    const float inv_norm = s_invnorm;
    const float mw0 = multi_w[0];
    const float mw1 = multi_w[1];
    const float4* __restrict__ pw4 = (const float4*)spw;

    // ---- Persistent work-queue loop ----
    for (;;) {
        if (tid == 0) s_task = atomicAdd(&g_task_counter, 1u);
        __syncthreads();
        const unsigned task = s_task;
        if (task >= TOTAL_TASKS) break;

        if (task < N_SCORE_TASKS) {
            // ============ SCORING TASK: batch b ============
            const int b = (int)task;
            const float* __restrict__ xb_sc = x_sc + (size_t)b * NN * DD;
            const float* __restrict__ xb_fc = x_fc + (size_t)b * NN * DD;

            for (int n = wid; n < NN; n += WARPS) {
                const float4* rs = (const float4*)(xb_sc + (size_t)n * DD);
                const float4* rf = (const float4*)(xb_fc + (size_t)n * DD);
                float dsc = 0.f, dfc = 0.f;
                #pragma unroll
                for (int i = 0; i < 8; i++) {
                    int j = lane + i * 32;
                    float4 a = rs[j];
                    float4 c = rf[j];
                    float4 p = pw4[j];
                    dsc += a.x * p.x + a.y * p.y + a.z * p.z + a.w * p.w;
                    dfc += c.x * p.x + c.y * p.y + c.z * p.z + c.w * p.w;
                }
                #pragma unroll
                for (int off = 16; off; off >>= 1) {
                    dsc += __shfl_xor_sync(0xffffffffu, dsc, off);
                    dfc += __shfl_xor_sync(0xffffffffu, dfc, off);
                }
                if (lane == 0) {
                    float t0 = tanhf(dsc * inv_norm);
                    float t1 = tanhf(dfc * inv_norm);
                    float z  = t0 * mw0 + t1 * mw1 + multi_b[n];
                    scores[n] = 1.f / (1.f + expf(-z));
                }
            }
            __syncthreads();

            // rank-count selection (stable descending argsort match)
            if (tid < NN) {
                float my = scores[tid];
                int rank = 0;
                #pragma unroll 10
                for (int j = 0; j < NN; j++) {
                    float sj = scores[j];
                    rank += (sj > my) || (sj == my && j < tid);
                }
                if (rank < KK) {
                    g_sel_idx[b][rank] = tid;
                    g_sel_w[b][rank]   = my;
                }
            }
            __syncthreads();
            if (tid == 0) {
                __threadfence();
                atomicExch(&g_flags[b], 1u);
            }
        } else {
            // ============ GATHER TASK: (batch, half) ============
            const unsigned g = task - N_SCORE_TASKS;
            const int b    = (int)(g >> 1);
            const int half = (int)(g & 1);   // 0 = sc, 1 = fc

            if (tid == 0) {
                while (atomicAdd(&g_flags[b], 0u) == 0u) { }
            }
            __syncthreads();
            __threadfence();

            const float* __restrict__ xb =
                (half == 0 ? x_sc : x_fc) + (size_t)b * NN * DD;
            float* __restrict__ ob = out
                + (size_t)half * BB * KK * DD + (size_t)b * KK * DD;

            for (int k = wid; k < KK; k += WARPS) {
                const int   n = g_sel_idx[b][k];
                const float w = g_sel_w[b][k];
                const float4* src = (const float4*)(xb + (size_t)n * DD);
                float4* dst = (float4*)(ob + (size_t)k * DD);
                #pragma unroll
                for (int i = 0; i < 8; i++) {
                    int j = lane + i * 32;
                    float4 v = src[j];
                    v.x *= w; v.y *= w; v.z *= w; v.w *= w;
                    dst[j] = v;
                }
            }
        }
        __syncthreads();   // protect s_task / scores reuse across iterations
    }
}

extern "C" void kernel_launch(void* const* d_in, const int* in_sizes, int n_in,
                              void* d_out, int out_size)
{
    const float* x_sc    = (const float*)d_in[0];
    const float* x_fc    = (const float*)d_in[1];
    const float* pool_w  = (const float*)d_in[2];
    const float* multi_w = (const float*)d_in[3];
    const float* multi_b = (const float*)d_in[4];
    float* out = (float*)d_out;

    static int grid = 0;
    if (grid == 0) {
        int sm = 0;
        cudaDeviceGetAttribute(&sm, cudaDevAttrMultiProcessorCount, 0);
        if (sm <= 0) sm = 148;
        grid = 2 * sm;
    }

    init_kernel<<<2, 256>>>();
    multig_pool_kernel<<<grid, THREADS>>>(x_sc, x_fc, pool_w, multi_w, multi_b, out);
}